// round 6
// baseline (speedup 1.0000x reference)
#include <cuda_runtime.h>
#include <cuda_fp16.h>
#include <math.h>
#include <stdint.h>

// ---------------------------------------------------------------------------
// SVM RBF inference: out = tanh(K @ (labels*relu(lambda)) + b)
//   K[b,n] = exp(-(||x_b||^2+||s_n||^2-2 x_b.s_n)/2), B=2048, N=50000, D=256
// v5: 48-wide augmented screening GEMM (46 data dims + 2 norm dims) so the
//     f16 HMMA accumulator equals -0.5*LB, LB a lower bound of the 256-dim
//     sqdist. Skip when LB >= ~34 (skipped mass < 1e-7, tol 7.6e-4); rare
//     candidates (P~4.5e-5/pair for N(0,1) data) take an exact fp32 256-dim
//     fixup from the ORIGINAL inputs -> correct for any input.
//     A fragments hoisted into registers for the whole CTA lifetime (A is
//     tile-invariant); B fragments register-double-buffered; 3-stage cp.async
//     ring with a single __syncthreads per tile. R5 ncu showed all pipes
//     <23% (latency-bound): this attacks the LDSM->MMA dependency stalls.
// ---------------------------------------------------------------------------

#define B_ROWS   2048
#define D_DIM    256
#define D_H      48              // screening K (46 data dims + 2 aug)
#define N_ROWS   50000
#define N_PAD    50176           // 392 * 128
#define N_TILES  392
#define BM       128
#define BN       128
#define THREADS  256
#define NSPLIT   27
#define GRID_X   (B_ROWS / BM)
#define TOTAL_CTAS (GRID_X * NSPLIT)
#define TACC     (-17.0f)        // acc = -0.5*LB; rescan if acc > TACC

#define A_STRIDE 112             // 48 fp16 + 8 pad (7*16B, 7 odd -> LDSM clean)
#define A_BYTES  (BM * A_STRIDE) // 14336
#define B_STG    (BN * A_STRIDE) // 14336
#define NSTG     3
#define SMEM_BYTES (A_BYTES + NSTG * B_STG) // 57344 -> 3 CTAs/SM

// Scratch (static device arrays: no allocation anywhere)
__device__ __align__(256) __half g_xh[B_ROWS * D_H];
__device__ __align__(256) __half g_sh[N_PAD * D_H];
__device__ __align__(256) float  g_w[N_PAD];
__device__ __align__(256) float  g_acc[B_ROWS];
__device__ int g_done;           // 0 at start of every call (self-resetting)

// ---------------------------------------------------------------------------
// Merged prep: one warp per row; augmented fp16 rows (dims 0..45 + 2 norm
// dims) + w; zeroes acc.
// ---------------------------------------------------------------------------
__global__ void prep(const float* __restrict__ x,
                     const float* __restrict__ ds,
                     const float* __restrict__ labels,
                     const float* __restrict__ lam) {
    const int lane = threadIdx.x & 31;
    const int gw = blockIdx.x * 8 + (threadIdx.x >> 5);
    if (gw < B_ROWS) {
        const int row = gw;
        float2 v = reinterpret_cast<const float2*>(x + (size_t)row * D_DIM)[lane];
        float ss = (lane < 23) ? (v.x * v.x + v.y * v.y) : 0.0f;
        #pragma unroll
        for (int o = 16; o > 0; o >>= 1) ss += __shfl_xor_sync(0xffffffffu, ss, o);
        __half2* dst = reinterpret_cast<__half2*>(g_xh + (size_t)row * D_H);
        if (lane < 23) dst[lane] = __float22half2_rn(v);
        else if (lane == 23) dst[23] = __floats2half2_rn(-0.5f * ss, 1.0f);
        if (lane == 0) g_acc[row] = 0.0f;
    } else {
        const int row = gw - B_ROWS;
        if (row >= N_PAD) return;
        __half2* dst = reinterpret_cast<__half2*>(g_sh + (size_t)row * D_H);
        if (row < N_ROWS) {
            float2 v = reinterpret_cast<const float2*>(ds + (size_t)row * D_DIM)[lane];
            float ss = (lane < 23) ? (v.x * v.x + v.y * v.y) : 0.0f;
            #pragma unroll
            for (int o = 16; o > 0; o >>= 1) ss += __shfl_xor_sync(0xffffffffu, ss, o);
            if (lane < 23) dst[lane] = __float22half2_rn(v);
            else if (lane == 23) dst[23] = __floats2half2_rn(1.0f, -0.5f * ss);
            if (lane == 0) g_w[row] = labels[row] * fmaxf(lam[row], 0.0f);
        } else {
            if (lane < 23) dst[lane] = __floats2half2_rn(0.0f, 0.0f);
            else if (lane == 23) dst[23] = __floats2half2_rn(1.0f, -30000.0f);
            if (lane == 0) g_w[row] = 0.0f;
        }
    }
}

// ---------------------------------------------------------------------------
// PTX helpers
// ---------------------------------------------------------------------------
__device__ __forceinline__ void cp16(uint32_t saddr, const void* gaddr) {
    asm volatile("cp.async.cg.shared.global [%0], [%1], 16;\n"
                 :: "r"(saddr), "l"(gaddr));
}
__device__ __forceinline__ void cp_commit() {
    asm volatile("cp.async.commit_group;\n");
}
template <int N>
__device__ __forceinline__ void cp_wait() {
    asm volatile("cp.async.wait_group %0;\n" :: "n"(N));
}
__device__ __forceinline__ void ldsm4(uint32_t* r, uint32_t addr) {
    asm volatile("ldmatrix.sync.aligned.m8n8.x4.shared.b16 {%0,%1,%2,%3}, [%4];"
                 : "=r"(r[0]), "=r"(r[1]), "=r"(r[2]), "=r"(r[3]) : "r"(addr));
}
__device__ __forceinline__ void mma_f16(uint32_t& d0, uint32_t& d1,
                                        const uint32_t a[4],
                                        uint32_t b0, uint32_t b1) {
    asm volatile(
        "mma.sync.aligned.m16n8k16.row.col.f16.f16.f16.f16 "
        "{%0,%1},{%2,%3,%4,%5},{%6,%7},{%0,%1};"
        : "+r"(d0), "+r"(d1)
        : "r"(a[0]), "r"(a[1]), "r"(a[2]), "r"(a[3]), "r"(b0), "r"(b1));
}

// Cold path: exact 256-dim fp32 squared distance from the ORIGINAL inputs.
__device__ __noinline__ float exact_sqdist(const float* __restrict__ xr,
                                           const float* __restrict__ sr) {
    float d2 = 0.0f;
    #pragma unroll 1
    for (int i = 0; i < D_DIM / 4; i++) {
        float4 a = reinterpret_cast<const float4*>(xr)[i];
        float4 b = reinterpret_cast<const float4*>(sr)[i];
        float dx = a.x - b.x, dy = a.y - b.y, dz = a.z - b.z, dw = a.w - b.w;
        d2 += dx * dx + dy * dy + dz * dz + dw * dw;
    }
    return d2;
}

// ---------------------------------------------------------------------------
// Main fused kernel (GEMM + screening epilogue + folded tanh finalize)
// ---------------------------------------------------------------------------
__global__ void __launch_bounds__(THREADS, 3)
svm_main(const float* __restrict__ xp, const float* __restrict__ sp,
         const float* __restrict__ bb, float* __restrict__ out) {
    extern __shared__ char smem[];
    uint32_t smem_u;
    asm("{ .reg .u64 t; cvta.to.shared.u64 t, %1; cvt.u32.u64 %0, t; }"
        : "=r"(smem_u) : "l"(smem));
    const uint32_t sA = smem_u;
    const uint32_t sB = smem_u + A_BYTES;

    const int tid  = threadIdx.x;
    const int lane = tid & 31;
    const int wid  = tid >> 5;
    const int wm   = wid & 3;   // 4 warps along M (32 rows each)
    const int wn   = wid >> 2;  // 2 warps along N (64 cols each)
    const int bm0  = blockIdx.x * BM;
    const int split = blockIdx.y;

    // ---- A tile (128 rows x 48 fp16) -> SMEM (group GA) ----
    {
        const __half* gx = g_xh + (size_t)bm0 * D_H;
        #pragma unroll
        for (int i = 0; i < 4; i++) {
            int u = tid + THREADS * i;          // 0..895 chunks of 16B
            if (u < 896) {
                int r = u / 7, c = u - r * 7;
                cp16(sA + r * A_STRIDE + c * 16, gx + (size_t)r * D_H + c * 8);
            }
        }
        cp_commit();
    }

    auto load_b = [&](int buf, int t0) {
        const __half* gs = g_sh + (size_t)t0 * BN * D_H;
        const uint32_t base = sB + buf * B_STG;
        #pragma unroll
        for (int i = 0; i < 4; i++) {
            int u = tid + THREADS * i;
            if (u < 896) {
                int r = u / 7, c = u - r * 7;
                cp16(base + r * A_STRIDE + c * 16, gs + (size_t)r * D_H + c * 8);
            }
        }
    };

    const int ntiles = (N_TILES - split + NSPLIT - 1) / NSPLIT;
    load_b(0, split); cp_commit();                         // G0
    if (ntiles > 1) load_b(1, split + NSPLIT);
    cp_commit();                                           // G1 (maybe empty)

    // ---- fragment addresses ----
    uint32_t a_base[2];
    #pragma unroll
    for (int mi = 0; mi < 2; mi++) {
        int r = wm * 32 + mi * 16 + (lane & 15);
        a_base[mi] = sA + r * A_STRIDE + (lane >> 4) * 16;
    }
    uint32_t b_row[4];
    {
        int grp = lane >> 3;
        #pragma unroll
        for (int p = 0; p < 4; p++) {
            int r = wn * 64 + p * 16 + (grp >> 1) * 8 + (lane & 7);
            b_row[p] = (uint32_t)(r * A_STRIDE + (grp & 1) * 16);
        }
    }

    // ---- hoist ALL A fragments (tile-invariant!) into registers ----
    cp_wait<2>();                  // GA complete (G0/G1 may be in flight)
    __syncthreads();
    uint32_t afr[3][2][4];         // [j][mi][reg]
    #pragma unroll
    for (int j = 0; j < 3; j++) {
        ldsm4(afr[j][0], a_base[0] + j * 32);
        ldsm4(afr[j][1], a_base[1] + j * 32);
    }

    float rsum[2][2] = {{0.0f, 0.0f}, {0.0f, 0.0f}};

    int t = split;
    for (int ti = 0; ti < ntiles; ti++, t += NSPLIT) {
        cp_wait<1>();              // tile ti's group complete
        __syncthreads();           // also protects ring buffer (ti+2)%3 reuse

        // prefetch tile ti+2 into the buffer last read at tile ti-1
        if (ti + 2 < ntiles) load_b((ti + 2) % NSTG, t + 2 * NSPLIT);
        cp_commit();               // always commit: keeps wait<1> exact

        const uint32_t stg = sB + (ti % NSTG) * B_STG;

        uint32_t acc[2][8][2];
        #pragma unroll
        for (int mi = 0; mi < 2; mi++)
            #pragma unroll
            for (int ni = 0; ni < 8; ni++) { acc[mi][ni][0] = 0u; acc[mi][ni][1] = 0u; }

        // ---- 12 (j,p) steps, B fragments register-double-buffered ----
        uint32_t bq[2][4];
        ldsm4(bq[0], stg + b_row[0]);            // (j=0, p=0)
        #pragma unroll
        for (int s = 0; s < 12; s++) {
            const int j = s >> 2, p = s & 3;
            if (s < 11) {
                const int s1 = s + 1;
                ldsm4(bq[s1 & 1], stg + b_row[s1 & 3] + (s1 >> 2) * 32);
            }
            const uint32_t* bc = bq[s & 1];
            mma_f16(acc[0][2*p][0],   acc[0][2*p][1],   afr[j][0], bc[0], bc[1]);
            mma_f16(acc[0][2*p+1][0], acc[0][2*p+1][1], afr[j][0], bc[2], bc[3]);
            mma_f16(acc[1][2*p][0],   acc[1][2*p][1],   afr[j][1], bc[0], bc[1]);
            mma_f16(acc[1][2*p+1][0], acc[1][2*p+1][1], afr[j][1], bc[2], bc[3]);
        }

        // ---- epilogue: acc == -0.5*LB; HMAX2 screen, cold exact fixup ----
        const int n0 = t * BN;
        #pragma unroll
        for (int mi = 0; mi < 2; mi++) {
            #pragma unroll
            for (int h = 0; h < 2; h++) {
                __half2 m = *reinterpret_cast<__half2*>(&acc[mi][0][h]);
                #pragma unroll
                for (int ni = 1; ni < 8; ni++)
                    m = __hmax2(m, *reinterpret_cast<__half2*>(&acc[mi][ni][h]));
                m = __hmax2(m, __lowhigh2highlow(m));
                if (__builtin_expect(__low2float(m) > TACC, 0)) {
                    const int row = bm0 + wm * 32 + mi * 16 + (lane >> 2) + 8 * h;
                    const float* xr = xp + (size_t)row * D_DIM;
                    #pragma unroll
                    for (int ni = 0; ni < 8; ni++) {
                        float2 c = __half22float2(
                            *reinterpret_cast<__half2*>(&acc[mi][ni][h]));
                        const int col = n0 + wn * 64 + ni * 8 + 2 * (lane & 3);
                        if (c.x > TACC && col < N_ROWS) {
                            float d2 = exact_sqdist(xr, sp + (size_t)col * D_DIM);
                            rsum[mi][h] += __expf(-0.5f * d2) * g_w[col];
                        }
                        if (c.y > TACC && col + 1 < N_ROWS) {
                            float d2 = exact_sqdist(xr, sp + (size_t)(col + 1) * D_DIM);
                            rsum[mi][h] += __expf(-0.5f * d2) * g_w[col + 1];
                        }
                    }
                }
            }
        }
    }

    // ---- row reduction: shfl within quad, one atomic per row per CTA ----
    #pragma unroll
    for (int mi = 0; mi < 2; mi++) {
        #pragma unroll
        for (int h = 0; h < 2; h++) {
            float v = rsum[mi][h];
            v += __shfl_xor_sync(0xffffffffu, v, 1);
            v += __shfl_xor_sync(0xffffffffu, v, 2);
            if ((lane & 3) == 0) {
                int r = bm0 + wm * 32 + mi * 16 + (lane >> 2) + h * 8;
                atomicAdd(&g_acc[r], v);
            }
        }
    }

    // ---- folded finalize: last CTA applies tanh(acc + b) ----
    __shared__ int s_last;
    __threadfence();
    __syncthreads();
    if (tid == 0) {
        int old = atomicAdd(&g_done, 1);
        s_last = (old == TOTAL_CTAS - 1);
    }
    __syncthreads();
    if (s_last) {
        __threadfence();
        const float bv = bb[0];
        #pragma unroll
        for (int i = 0; i < B_ROWS / THREADS; i++) {
            int r = tid + i * THREADS;
            out[r] = tanhf(g_acc[r] + bv);
        }
        if (tid == 0) g_done = 0;   // self-reset for next graph replay
    }
}

// ---------------------------------------------------------------------------
extern "C" void kernel_launch(void* const* d_in, const int* in_sizes, int n_in,
                              void* d_out, int out_size) {
    const float* x      = (const float*)d_in[0];
    const float* ds     = (const float*)d_in[1];
    const float* labels = (const float*)d_in[2];
    const float* lam    = (const float*)d_in[3];
    const float* b      = (const float*)d_in[4];
    float* out = (float*)d_out;
    (void)in_sizes; (void)n_in; (void)out_size;

    cudaFuncSetAttribute(svm_main, cudaFuncAttributeMaxDynamicSharedMemorySize,
                         SMEM_BYTES);

    prep<<<(B_ROWS + N_PAD + 7) / 8, 256>>>(x, ds, labels, lam);

    dim3 grid(GRID_X, NSPLIT);
    svm_main<<<grid, THREADS, SMEM_BYTES>>>(x, ds, b, out);
}

// round 7
// speedup vs baseline: 1.0632x; 1.0632x over previous
#include <cuda_runtime.h>
#include <cuda_fp16.h>
#include <math.h>
#include <stdint.h>

// ---------------------------------------------------------------------------
// SVM RBF inference: out = tanh(K @ (labels*relu(lambda)) + b)
//   K[b,n] = exp(-(||x_b||^2+||s_n||^2-2 x_b.s_n)/2), B=2048, N=50000, D=256
// v6: R5's proven schedule (batched per-j LDSM -> MLP~6) + two changes:
//     (1) 48-wide augmented screening GEMM (46 data dims + 2 norm dims):
//         f16 HMMA acc == -0.5*LB, LB lower-bounds the 256-dim sqdist.
//         Skip when LB >= 34 (skipped mass < 1e-7 vs tol 7.6e-4); rare
//         candidates take an exact fp32 256-dim fixup from ORIGINAL inputs.
//     (2) pair-processing: 2 tiles per barrier pair, 4-stage cp.async ring
//         -> half the sync/convoy frequency of R5.
//     R6 lesson: do NOT hoist A fragments / serialize B prefetch — the
//     independent per-j LDSM batch is what hides the 29-cyc LDS latency.
// ---------------------------------------------------------------------------

#define B_ROWS   2048
#define D_DIM    256
#define D_H      48              // screening K (46 data dims + 2 aug)
#define N_ROWS   50000
#define N_PAD    50176           // 392 * 128
#define N_TILES  392
#define BM       128
#define BN       128
#define THREADS  256
#define NSPLIT   27
#define GRID_X   (B_ROWS / BM)
#define TOTAL_CTAS (GRID_X * NSPLIT)
#define TACC     (-17.0f)        // acc = -0.5*LB; rescan if acc > TACC

#define A_STRIDE 112             // 48 fp16 + 8 pad (7*16B -> LDSM conflict-free)
#define A_BYTES  (BM * A_STRIDE) // 14336
#define B_STG    (BN * A_STRIDE) // 14336
#define NSTG     4               // 2 pairs in flight
#define SMEM_BYTES (A_BYTES + NSTG * B_STG) // 71680 -> 3 CTAs/SM

// Scratch (static device arrays: no allocation anywhere)
__device__ __align__(256) __half g_xh[B_ROWS * D_H];
__device__ __align__(256) __half g_sh[N_PAD * D_H];
__device__ __align__(256) float  g_w[N_PAD];
__device__ __align__(256) float  g_acc[B_ROWS];
__device__ int g_done;           // 0 at start of every call (self-resetting)

// ---------------------------------------------------------------------------
// Merged prep: one warp per row; augmented fp16 rows + w; zeroes acc.
// ---------------------------------------------------------------------------
__global__ void prep(const float* __restrict__ x,
                     const float* __restrict__ ds,
                     const float* __restrict__ labels,
                     const float* __restrict__ lam) {
    const int lane = threadIdx.x & 31;
    const int gw = blockIdx.x * 8 + (threadIdx.x >> 5);
    if (gw < B_ROWS) {
        const int row = gw;
        float2 v = reinterpret_cast<const float2*>(x + (size_t)row * D_DIM)[lane];
        float ss = (lane < 23) ? (v.x * v.x + v.y * v.y) : 0.0f;
        #pragma unroll
        for (int o = 16; o > 0; o >>= 1) ss += __shfl_xor_sync(0xffffffffu, ss, o);
        __half2* dst = reinterpret_cast<__half2*>(g_xh + (size_t)row * D_H);
        if (lane < 23) dst[lane] = __float22half2_rn(v);
        else if (lane == 23) dst[23] = __floats2half2_rn(-0.5f * ss, 1.0f);
        if (lane == 0) g_acc[row] = 0.0f;
    } else {
        const int row = gw - B_ROWS;
        if (row >= N_PAD) return;
        __half2* dst = reinterpret_cast<__half2*>(g_sh + (size_t)row * D_H);
        if (row < N_ROWS) {
            float2 v = reinterpret_cast<const float2*>(ds + (size_t)row * D_DIM)[lane];
            float ss = (lane < 23) ? (v.x * v.x + v.y * v.y) : 0.0f;
            #pragma unroll
            for (int o = 16; o > 0; o >>= 1) ss += __shfl_xor_sync(0xffffffffu, ss, o);
            if (lane < 23) dst[lane] = __float22half2_rn(v);
            else if (lane == 23) dst[23] = __floats2half2_rn(1.0f, -0.5f * ss);
            if (lane == 0) g_w[row] = labels[row] * fmaxf(lam[row], 0.0f);
        } else {
            if (lane < 23) dst[lane] = __floats2half2_rn(0.0f, 0.0f);
            else if (lane == 23) dst[23] = __floats2half2_rn(1.0f, -30000.0f);
            if (lane == 0) g_w[row] = 0.0f;
        }
    }
}

// ---------------------------------------------------------------------------
// PTX helpers
// ---------------------------------------------------------------------------
__device__ __forceinline__ void cp16(uint32_t saddr, const void* gaddr) {
    asm volatile("cp.async.cg.shared.global [%0], [%1], 16;\n"
                 :: "r"(saddr), "l"(gaddr));
}
__device__ __forceinline__ void cp_commit() {
    asm volatile("cp.async.commit_group;\n");
}
template <int N>
__device__ __forceinline__ void cp_wait() {
    asm volatile("cp.async.wait_group %0;\n" :: "n"(N));
}
__device__ __forceinline__ void ldsm4(uint32_t* r, uint32_t addr) {
    asm volatile("ldmatrix.sync.aligned.m8n8.x4.shared.b16 {%0,%1,%2,%3}, [%4];"
                 : "=r"(r[0]), "=r"(r[1]), "=r"(r[2]), "=r"(r[3]) : "r"(addr));
}
__device__ __forceinline__ void mma_f16(uint32_t& d0, uint32_t& d1,
                                        const uint32_t a[4],
                                        uint32_t b0, uint32_t b1) {
    asm volatile(
        "mma.sync.aligned.m16n8k16.row.col.f16.f16.f16.f16 "
        "{%0,%1},{%2,%3,%4,%5},{%6,%7},{%0,%1};"
        : "+r"(d0), "+r"(d1)
        : "r"(a[0]), "r"(a[1]), "r"(a[2]), "r"(a[3]), "r"(b0), "r"(b1));
}

// Cold path: exact 256-dim fp32 squared distance from the ORIGINAL inputs.
__device__ __noinline__ float exact_sqdist(const float* __restrict__ xr,
                                           const float* __restrict__ sr) {
    float d2 = 0.0f;
    #pragma unroll 1
    for (int i = 0; i < D_DIM / 4; i++) {
        float4 a = reinterpret_cast<const float4*>(xr)[i];
        float4 b = reinterpret_cast<const float4*>(sr)[i];
        float dx = a.x - b.x, dy = a.y - b.y, dz = a.z - b.z, dw = a.w - b.w;
        d2 += dx * dx + dy * dy + dz * dz + dw * dw;
    }
    return d2;
}

// ---------------------------------------------------------------------------
// Main fused kernel (GEMM + screening epilogue + folded tanh finalize)
// ---------------------------------------------------------------------------
__global__ void __launch_bounds__(THREADS, 3)
svm_main(const float* __restrict__ xp, const float* __restrict__ sp,
         const float* __restrict__ bb, float* __restrict__ out) {
    extern __shared__ char smem[];
    uint32_t smem_u;
    asm("{ .reg .u64 t; cvta.to.shared.u64 t, %1; cvt.u32.u64 %0, t; }"
        : "=r"(smem_u) : "l"(smem));
    const uint32_t sA = smem_u;
    const uint32_t sB = smem_u + A_BYTES;

    const int tid  = threadIdx.x;
    const int lane = tid & 31;
    const int wid  = tid >> 5;
    const int wm   = wid & 3;   // 4 warps along M (32 rows each)
    const int wn   = wid >> 2;  // 2 warps along N (64 cols each)
    const int bm0  = blockIdx.x * BM;
    const int split = blockIdx.y;

    const int ntiles = (N_TILES - split + NSPLIT - 1) / NSPLIT;
    const int npairs = (ntiles + 1) >> 1;

    // ---- A tile (128 rows x 48 fp16) -> SMEM ----
    {
        const __half* gx = g_xh + (size_t)bm0 * D_H;
        #pragma unroll
        for (int i = 0; i < 4; i++) {
            int u = tid + THREADS * i;          // 16B chunks, 896 total
            if (u < 896) {
                int r = u / 7, c = u - r * 7;
                cp16(sA + r * A_STRIDE + c * 16, gx + (size_t)r * D_H + c * 8);
            }
        }
        cp_commit();                            // GA
    }

    auto load_b = [&](int stage, int t0) {
        const __half* gs = g_sh + (size_t)t0 * BN * D_H;
        const uint32_t base = sB + stage * B_STG;
        #pragma unroll
        for (int i = 0; i < 4; i++) {
            int u = tid + THREADS * i;
            if (u < 896) {
                int r = u / 7, c = u - r * 7;
                cp16(base + r * A_STRIDE + c * 16, gs + (size_t)r * D_H + c * 8);
            }
        }
    };
    // one commit per pair; guarded per tile
    auto load_pair = [&](int pi) {
        #pragma unroll
        for (int k = 0; k < 2; k++) {
            int ti = 2 * pi + k;
            if (ti < ntiles) load_b((2 * pi + k) & 3, split + ti * NSPLIT);
        }
    };

    load_pair(0); cp_commit();                  // P0
    load_pair(1); cp_commit();                  // P1

    // ---- fragment addresses ----
    uint32_t a_base[2];
    #pragma unroll
    for (int mi = 0; mi < 2; mi++) {
        int r = wm * 32 + mi * 16 + (lane & 15);
        a_base[mi] = sA + r * A_STRIDE + (lane >> 4) * 16;
    }
    uint32_t b_row[4];
    {
        int grp = lane >> 3;
        #pragma unroll
        for (int p = 0; p < 4; p++) {
            int r = wn * 64 + p * 16 + (grp >> 1) * 8 + (lane & 7);
            b_row[p] = (uint32_t)(r * A_STRIDE + (grp & 1) * 16);
        }
    }

    float rsum[2][2] = {{0.0f, 0.0f}, {0.0f, 0.0f}};

    for (int pi = 0; pi < npairs; pi++) {
        cp_wait<1>();              // pair pi's group complete
        __syncthreads();

        #pragma unroll
        for (int k = 0; k < 2; k++) {
            const int ti = 2 * pi + k;
            if (ti >= ntiles) break;
            const int t = split + ti * NSPLIT;
            const uint32_t stg = sB + ((2 * pi + k) & 3) * B_STG;

            uint32_t acc[2][8][2];
            #pragma unroll
            for (int mi = 0; mi < 2; mi++)
                #pragma unroll
                for (int ni = 0; ni < 8; ni++) { acc[mi][ni][0] = 0u; acc[mi][ni][1] = 0u; }

            // ---- R5-style: per j, batch 2 A + 4 B LDSMs (MLP~6), then MMAs
            #pragma unroll
            for (int j = 0; j < 3; j++) {        // 3 k16 steps over D_H=48
                uint32_t a[2][4];
                ldsm4(a[0], a_base[0] + j * 32);
                ldsm4(a[1], a_base[1] + j * 32);
                #pragma unroll
                for (int p = 0; p < 4; p++) {
                    uint32_t bbq[4];
                    ldsm4(bbq, stg + b_row[p] + j * 32);
                    mma_f16(acc[0][2*p][0],   acc[0][2*p][1],   a[0], bbq[0], bbq[1]);
                    mma_f16(acc[0][2*p+1][0], acc[0][2*p+1][1], a[0], bbq[2], bbq[3]);
                    mma_f16(acc[1][2*p][0],   acc[1][2*p][1],   a[1], bbq[0], bbq[1]);
                    mma_f16(acc[1][2*p+1][0], acc[1][2*p+1][1], a[1], bbq[2], bbq[3]);
                }
            }

            // ---- epilogue: acc == -0.5*LB; HMAX2 screen, cold exact fixup
            const int n0 = t * BN;
            #pragma unroll
            for (int mi = 0; mi < 2; mi++) {
                #pragma unroll
                for (int h = 0; h < 2; h++) {
                    __half2 m = *reinterpret_cast<__half2*>(&acc[mi][0][h]);
                    #pragma unroll
                    for (int ni = 1; ni < 8; ni++)
                        m = __hmax2(m, *reinterpret_cast<__half2*>(&acc[mi][ni][h]));
                    m = __hmax2(m, __lowhigh2highlow(m));
                    if (__builtin_expect(__low2float(m) > TACC, 0)) {
                        const int row = bm0 + wm * 32 + mi * 16 + (lane >> 2) + 8 * h;
                        const float* xr = xp + (size_t)row * D_DIM;
                        #pragma unroll
                        for (int ni = 0; ni < 8; ni++) {
                            float2 c = __half22float2(
                                *reinterpret_cast<__half2*>(&acc[mi][ni][h]));
                            const int col = n0 + wn * 64 + ni * 8 + 2 * (lane & 3);
                            if (c.x > TACC && col < N_ROWS) {
                                float d2 = exact_sqdist(xr, sp + (size_t)col * D_DIM);
                                rsum[mi][h] += __expf(-0.5f * d2) * g_w[col];
                            }
                            if (c.y > TACC && col + 1 < N_ROWS) {
                                float d2 = exact_sqdist(xr, sp + (size_t)(col + 1) * D_DIM);
                                rsum[mi][h] += __expf(-0.5f * d2) * g_w[col + 1];
                            }
                        }
                    }
                }
            }
        }

        __syncthreads();           // all warps done reading pair pi's stages
        load_pair(pi + 2);         // refill the 2 stages just freed
        cp_commit();               // exactly one commit per iteration
    }

    // ---- row reduction: shfl within quad, one atomic per row per CTA ----
    #pragma unroll
    for (int mi = 0; mi < 2; mi++) {
        #pragma unroll
        for (int h = 0; h < 2; h++) {
            float v = rsum[mi][h];
            v += __shfl_xor_sync(0xffffffffu, v, 1);
            v += __shfl_xor_sync(0xffffffffu, v, 2);
            if ((lane & 3) == 0) {
                int r = bm0 + wm * 32 + mi * 16 + (lane >> 2) + h * 8;
                atomicAdd(&g_acc[r], v);
            }
        }
    }

    // ---- folded finalize: last CTA applies tanh(acc + b) ----
    __shared__ int s_last;
    __threadfence();
    __syncthreads();
    if (tid == 0) {
        int old = atomicAdd(&g_done, 1);
        s_last = (old == TOTAL_CTAS - 1);
    }
    __syncthreads();
    if (s_last) {
        __threadfence();
        const float bv = bb[0];
        #pragma unroll
        for (int i = 0; i < B_ROWS / THREADS; i++) {
            int r = tid + i * THREADS;
            out[r] = tanhf(g_acc[r] + bv);
        }
        if (tid == 0) g_done = 0;   // self-reset for next graph replay
    }
}

// ---------------------------------------------------------------------------
extern "C" void kernel_launch(void* const* d_in, const int* in_sizes, int n_in,
                              void* d_out, int out_size) {
    const float* x      = (const float*)d_in[0];
    const float* ds     = (const float*)d_in[1];
    const float* labels = (const float*)d_in[2];
    const float* lam    = (const float*)d_in[3];
    const float* b      = (const float*)d_in[4];
    float* out = (float*)d_out;
    (void)in_sizes; (void)n_in; (void)out_size;

    cudaFuncSetAttribute(svm_main, cudaFuncAttributeMaxDynamicSharedMemorySize,
                         SMEM_BYTES);

    prep<<<(B_ROWS + N_PAD + 7) / 8, 256>>>(x, ds, labels, lam);

    dim3 grid(GRID_X, NSPLIT);
    svm_main<<<grid, THREADS, SMEM_BYTES>>>(x, ds, b, out);
}

// round 8
// speedup vs baseline: 1.5440x; 1.4523x over previous
#include <cuda_runtime.h>
#include <cuda_fp16.h>
#include <math.h>
#include <stdint.h>

// ---------------------------------------------------------------------------
// SVM RBF inference: out = tanh(K @ (labels*relu(lambda)) + b)
//   K[b,n] = exp(-(||x_b||^2+||s_n||^2-2 x_b.s_n)/2), B=2048, N=50000, D=256
// v7: R5 (proven 86.8us) + ONE change: 3-stage cp.async ring with a single
//     __syncthreads per tile and top-of-tile refill. Everything else is the
//     R5 schedule verbatim.
//     Augmented 64-wide screening GEMM: dims 0..61 raw fp16 data, dims 62/63
//     encode norms so the f16 HMMA acc == -0.5*LB (LB = 62-dim sqdist, a
//     lower bound of the 256-dim sqdist). Skip when LB >= 51 (skipped mass
//     < 1e-11 vs tol 7.6e-4); rare candidates (P~2-5e-4/pair, N(0,1) data)
//     take an exact fp32 256-dim fixup from ORIGINAL inputs -> correct for
//     any input. tanh finalize folded into last-arriving CTA.
//     R6/R7 lessons: D_H=48 regressed (mechanism unclear) — keep 64; do not
//     serialize the per-j LDSM batch (it provides the latency-hiding MLP).
// ---------------------------------------------------------------------------

#define B_ROWS   2048
#define D_DIM    256
#define D_H      64              // screening K (62 data dims + 2 aug)
#define N_ROWS   50000
#define N_PAD    50176           // 392 * 128
#define N_TILES  392
#define BM       128
#define BN       128
#define THREADS  256
#define NSPLIT   27
#define GRID_X   (B_ROWS / BM)
#define TOTAL_CTAS (GRID_X * NSPLIT)
#define TACC     (-25.5f)        // acc = -0.5*LB; rescan if acc > TACC

#define A_STRIDE 144             // 64 fp16 + 8 pad (9*16B: conflict-free LDSM)
#define A_BYTES  (BM * A_STRIDE) // 18432
#define B_STG    (BN * A_STRIDE) // 18432
#define NSTG     3
#define SMEM_BYTES (A_BYTES + NSTG * B_STG) // 73728 -> 3 CTAs/SM (216KB/228KB)

// Scratch (static device arrays: no allocation anywhere)
__device__ __align__(256) __half g_xh[B_ROWS * D_H];
__device__ __align__(256) __half g_sh[N_PAD * D_H];
__device__ __align__(256) float  g_w[N_PAD];
__device__ __align__(256) float  g_acc[B_ROWS];
__device__ int g_done;           // 0 at start of every call (self-resetting)

// ---------------------------------------------------------------------------
// Merged prep: one warp per row; builds augmented fp16 rows + w; zeroes acc.
// ---------------------------------------------------------------------------
__global__ void prep(const float* __restrict__ x,
                     const float* __restrict__ ds,
                     const float* __restrict__ labels,
                     const float* __restrict__ lam) {
    const int lane = threadIdx.x & 31;
    const int gw = blockIdx.x * 8 + (threadIdx.x >> 5);
    if (gw < B_ROWS) {
        const int row = gw;
        float2 v = reinterpret_cast<const float2*>(x + (size_t)row * D_DIM)[lane];
        float ss = (lane < 31) ? (v.x * v.x + v.y * v.y) : 0.0f;
        #pragma unroll
        for (int o = 16; o > 0; o >>= 1) ss += __shfl_xor_sync(0xffffffffu, ss, o);
        __half2 out = (lane < 31) ? __float22half2_rn(v)
                                  : __floats2half2_rn(-0.5f * ss, 1.0f);
        reinterpret_cast<__half2*>(g_xh + (size_t)row * D_H)[lane] = out;
        if (lane == 0) g_acc[row] = 0.0f;
    } else {
        const int row = gw - B_ROWS;
        if (row >= N_PAD) return;
        if (row < N_ROWS) {
            float2 v = reinterpret_cast<const float2*>(ds + (size_t)row * D_DIM)[lane];
            float ss = (lane < 31) ? (v.x * v.x + v.y * v.y) : 0.0f;
            #pragma unroll
            for (int o = 16; o > 0; o >>= 1) ss += __shfl_xor_sync(0xffffffffu, ss, o);
            __half2 out = (lane < 31) ? __float22half2_rn(v)
                                      : __floats2half2_rn(1.0f, -0.5f * ss);
            reinterpret_cast<__half2*>(g_sh + (size_t)row * D_H)[lane] = out;
            if (lane == 0) g_w[row] = labels[row] * fmaxf(lam[row], 0.0f);
        } else {
            __half2 out = (lane < 31) ? __floats2half2_rn(0.0f, 0.0f)
                                      : __floats2half2_rn(1.0f, -30000.0f);
            reinterpret_cast<__half2*>(g_sh + (size_t)row * D_H)[lane] = out;
            if (lane == 0) g_w[row] = 0.0f;
        }
    }
}

// ---------------------------------------------------------------------------
// PTX helpers
// ---------------------------------------------------------------------------
__device__ __forceinline__ void cp16(uint32_t saddr, const void* gaddr) {
    asm volatile("cp.async.cg.shared.global [%0], [%1], 16;\n"
                 :: "r"(saddr), "l"(gaddr));
}
__device__ __forceinline__ void cp_commit() {
    asm volatile("cp.async.commit_group;\n");
}
template <int N>
__device__ __forceinline__ void cp_wait() {
    asm volatile("cp.async.wait_group %0;\n" :: "n"(N));
}
__device__ __forceinline__ void ldsm4(uint32_t* r, uint32_t addr) {
    asm volatile("ldmatrix.sync.aligned.m8n8.x4.shared.b16 {%0,%1,%2,%3}, [%4];"
                 : "=r"(r[0]), "=r"(r[1]), "=r"(r[2]), "=r"(r[3]) : "r"(addr));
}
__device__ __forceinline__ void mma_f16(uint32_t& d0, uint32_t& d1,
                                        const uint32_t a[4],
                                        uint32_t b0, uint32_t b1) {
    asm volatile(
        "mma.sync.aligned.m16n8k16.row.col.f16.f16.f16.f16 "
        "{%0,%1},{%2,%3,%4,%5},{%6,%7},{%0,%1};"
        : "+r"(d0), "+r"(d1)
        : "r"(a[0]), "r"(a[1]), "r"(a[2]), "r"(a[3]), "r"(b0), "r"(b1));
}

// Cold path: exact 256-dim fp32 squared distance from the ORIGINAL inputs.
__device__ __noinline__ float exact_sqdist(const float* __restrict__ xr,
                                           const float* __restrict__ sr) {
    float d2 = 0.0f;
    #pragma unroll 1
    for (int i = 0; i < D_DIM / 4; i++) {
        float4 a = reinterpret_cast<const float4*>(xr)[i];
        float4 b = reinterpret_cast<const float4*>(sr)[i];
        float dx = a.x - b.x, dy = a.y - b.y, dz = a.z - b.z, dw = a.w - b.w;
        d2 += dx * dx + dy * dy + dz * dz + dw * dw;
    }
    return d2;
}

// ---------------------------------------------------------------------------
// Main fused kernel (GEMM + screening epilogue + folded tanh finalize)
// ---------------------------------------------------------------------------
__global__ void __launch_bounds__(THREADS, 3)
svm_main(const float* __restrict__ xp, const float* __restrict__ sp,
         const float* __restrict__ bb, float* __restrict__ out) {
    extern __shared__ char smem[];
    uint32_t smem_u;
    asm("{ .reg .u64 t; cvta.to.shared.u64 t, %1; cvt.u32.u64 %0, t; }"
        : "=r"(smem_u) : "l"(smem));
    const uint32_t sA = smem_u;
    const uint32_t sB = smem_u + A_BYTES;

    const int tid  = threadIdx.x;
    const int lane = tid & 31;
    const int wid  = tid >> 5;
    const int wm   = wid & 3;   // 4 warps along M (32 rows each)
    const int wn   = wid >> 2;  // 2 warps along N (64 cols each)
    const int bm0  = blockIdx.x * BM;
    const int split = blockIdx.y;

    // ---- A tile load (128 rows x 64 fp16), resident ----
    {
        const __half* gx = g_xh + (size_t)bm0 * D_H;
        #pragma unroll
        for (int i = 0; i < 4; i++) {
            int u = tid + THREADS * i;      // 0..1023 16B chunks
            int r = u >> 3, c = u & 7;
            cp16(sA + r * A_STRIDE + c * 16, gx + (size_t)r * D_H + c * 8);
        }
        cp_commit();                        // GA
    }

    auto load_b = [&](int buf, int t0) {
        const __half* gs = g_sh + (size_t)t0 * BN * D_H;
        const uint32_t base = sB + buf * B_STG;
        #pragma unroll
        for (int i = 0; i < 4; i++) {
            int u = tid + THREADS * i;
            int r = u >> 3, c = u & 7;
            cp16(base + r * A_STRIDE + c * 16, gs + (size_t)r * D_H + c * 8);
        }
    };

    const int ntiles = (N_TILES - split + NSPLIT - 1) / NSPLIT;
    load_b(0, split); cp_commit();          // G0
    if (ntiles > 1) load_b(1, split + NSPLIT);
    cp_commit();                            // G1 (possibly empty)

    // ---- hoisted LDSM addresses ----
    uint32_t a_base[2];
    #pragma unroll
    for (int mi = 0; mi < 2; mi++) {
        int r = wm * 32 + mi * 16 + (lane & 15);
        a_base[mi] = sA + r * A_STRIDE + (lane >> 4) * 16;
    }
    uint32_t b_row[4];
    {
        int grp = lane >> 3;
        #pragma unroll
        for (int p = 0; p < 4; p++) {
            int r = wn * 64 + p * 16 + (grp >> 1) * 8 + (lane & 7);
            b_row[p] = (uint32_t)(r * A_STRIDE + (grp & 1) * 16);
        }
    }

    float rsum[2][2] = {{0.0f, 0.0f}, {0.0f, 0.0f}};

    int t = split;
    for (int ti = 0; ti < ntiles; ti++, t += NSPLIT) {
        cp_wait<1>();            // tile ti's group complete (ti+1 in flight)
        __syncthreads();         // single barrier per tile: also guarantees all
                                 // warps finished reading stage (ti+2)%3 (last
                                 // read at tile ti-1) before we refill it below

        // top-of-tile refill: stage for tile ti+2 (longer overlap with compute)
        if (ti + 2 < ntiles) load_b((ti + 2) % NSTG, t + 2 * NSPLIT);
        cp_commit();             // always commit (keeps wait<1> bookkeeping exact)

        const uint32_t stg = sB + (ti % NSTG) * B_STG;

        uint32_t acc[2][8][2];
        #pragma unroll
        for (int mi = 0; mi < 2; mi++)
            #pragma unroll
            for (int ni = 0; ni < 8; ni++) { acc[mi][ni][0] = 0u; acc[mi][ni][1] = 0u; }

        #pragma unroll
        for (int j = 0; j < 4; j++) {        // 4 k16 steps over D_H=64
            uint32_t a[2][4];
            ldsm4(a[0], a_base[0] + j * 32);
            ldsm4(a[1], a_base[1] + j * 32);
            #pragma unroll
            for (int p = 0; p < 4; p++) {
                uint32_t bbq[4];
                ldsm4(bbq, stg + b_row[p] + j * 32);
                mma_f16(acc[0][2 * p][0],     acc[0][2 * p][1],     a[0], bbq[0], bbq[1]);
                mma_f16(acc[0][2 * p + 1][0], acc[0][2 * p + 1][1], a[0], bbq[2], bbq[3]);
                mma_f16(acc[1][2 * p][0],     acc[1][2 * p][1],     a[1], bbq[0], bbq[1]);
                mma_f16(acc[1][2 * p + 1][0], acc[1][2 * p + 1][1], a[1], bbq[2], bbq[3]);
            }
        }

        // ---- epilogue: acc == -0.5*LB; HMAX2 tree screen, cold exact fixup ----
        const int n0 = t * BN;
        #pragma unroll
        for (int mi = 0; mi < 2; mi++) {
            #pragma unroll
            for (int h = 0; h < 2; h++) {
                __half2 m0 = __hmax2(*reinterpret_cast<__half2*>(&acc[mi][0][h]),
                                     *reinterpret_cast<__half2*>(&acc[mi][1][h]));
                __half2 m1 = __hmax2(*reinterpret_cast<__half2*>(&acc[mi][2][h]),
                                     *reinterpret_cast<__half2*>(&acc[mi][3][h]));
                __half2 m2 = __hmax2(*reinterpret_cast<__half2*>(&acc[mi][4][h]),
                                     *reinterpret_cast<__half2*>(&acc[mi][5][h]));
                __half2 m3 = __hmax2(*reinterpret_cast<__half2*>(&acc[mi][6][h]),
                                     *reinterpret_cast<__half2*>(&acc[mi][7][h]));
                __half2 m = __hmax2(__hmax2(m0, m1), __hmax2(m2, m3));
                m = __hmax2(m, __lowhigh2highlow(m));
                if (__builtin_expect(__low2float(m) > TACC, 0)) {
                    const int row = bm0 + wm * 32 + mi * 16 + (lane >> 2) + 8 * h;
                    const float* xr = xp + (size_t)row * D_DIM;
                    #pragma unroll
                    for (int ni = 0; ni < 8; ni++) {
                        float2 c = __half22float2(
                            *reinterpret_cast<__half2*>(&acc[mi][ni][h]));
                        const int col = n0 + wn * 64 + ni * 8 + 2 * (lane & 3);
                        if (c.x > TACC && col < N_ROWS) {
                            float d2 = exact_sqdist(xr, sp + (size_t)col * D_DIM);
                            rsum[mi][h] += __expf(-0.5f * d2) * g_w[col];
                        }
                        if (c.y > TACC && col + 1 < N_ROWS) {
                            float d2 = exact_sqdist(xr, sp + (size_t)(col + 1) * D_DIM);
                            rsum[mi][h] += __expf(-0.5f * d2) * g_w[col + 1];
                        }
                    }
                }
            }
        }
    }

    // ---- row reduction: shfl within quad, one atomic per row per CTA ----
    #pragma unroll
    for (int mi = 0; mi < 2; mi++) {
        #pragma unroll
        for (int h = 0; h < 2; h++) {
            float v = rsum[mi][h];
            v += __shfl_xor_sync(0xffffffffu, v, 1);
            v += __shfl_xor_sync(0xffffffffu, v, 2);
            if ((lane & 3) == 0) {
                int r = bm0 + wm * 32 + mi * 16 + (lane >> 2) + h * 8;
                atomicAdd(&g_acc[r], v);
            }
        }
    }

    // ---- folded finalize: last CTA applies tanh(acc + b) ----
    __shared__ int s_last;
    __threadfence();
    __syncthreads();
    if (tid == 0) {
        int old = atomicAdd(&g_done, 1);
        s_last = (old == TOTAL_CTAS - 1);
    }
    __syncthreads();
    if (s_last) {
        __threadfence();
        const float bv = bb[0];
        #pragma unroll
        for (int i = 0; i < B_ROWS / THREADS; i++) {
            int r = tid + i * THREADS;
            out[r] = tanhf(g_acc[r] + bv);
        }
        if (tid == 0) g_done = 0;   // self-reset for next graph replay
    }
}

// ---------------------------------------------------------------------------
extern "C" void kernel_launch(void* const* d_in, const int* in_sizes, int n_in,
                              void* d_out, int out_size) {
    const float* x      = (const float*)d_in[0];
    const float* ds     = (const float*)d_in[1];
    const float* labels = (const float*)d_in[2];
    const float* lam    = (const float*)d_in[3];
    const float* b      = (const float*)d_in[4];
    float* out = (float*)d_out;
    (void)in_sizes; (void)n_in; (void)out_size;

    cudaFuncSetAttribute(svm_main, cudaFuncAttributeMaxDynamicSharedMemorySize,
                         SMEM_BYTES);

    prep<<<(B_ROWS + N_PAD + 7) / 8, 256>>>(x, ds, labels, lam);

    dim3 grid(GRID_X, NSPLIT);
    svm_main<<<grid, THREADS, SMEM_BYTES>>>(x, ds, b, out);
}